// round 1
// baseline (speedup 1.0000x reference)
#include <cuda_runtime.h>

// ---------------------------------------------------------------------------
// Fully-fused recurrent relational network.
// One CTA = 4 graphs (32 node rows). h/x/A/B live in smem for all 8 steps.
//
// Key algebra:
//   msg hidden(i,j) = relu(A_i + B_j + b1),  A = h@W1[0:128], B = h@W1[128:256]
//   m_agg[i] = (sum_{j!=i} relu(A_i+B_j+b1)) @ msg_w2 + 7*msg_b2
// so the per-edge MLP collapses to elementwise ops + per-node GEMMs.
// ---------------------------------------------------------------------------

#define THREADS 128
#define NG      4      // graphs per CTA
#define MROWS   32     // 8 * NG node rows per CTA
#define BS      2048
#define NSTEPS  8
#define H       128

union F2 { float2 f; unsigned long long u; };

__device__ __forceinline__ F2 f2fma(F2 a, F2 b, F2 c) {
    F2 d;
    asm("fma.rn.f32x2 %0, %1, %2, %3;" : "=l"(d.u) : "l"(a.u), "l"(b.u), "l"(c.u));
    return d;
}

__device__ __forceinline__ F2 f2bcast(float x) {
    F2 r;
    unsigned xi = __float_as_uint(x);
    asm("mov.b64 %0, {%1, %1};" : "=l"(r.u) : "r"(xi));
    return r;
}

// Accumulate  acc[4 rows][4 col-pairs] += in(smem)[r0..r0+3][:] @ W(gmem 128x128)
__device__ __forceinline__ void gemm_acc(const float* __restrict__ in,
                                         const float* __restrict__ W,
                                         F2 (&acc)[4][4], int r0, int c0) {
#pragma unroll 4
    for (int k = 0; k < H; ++k) {
        float4 w0 = *reinterpret_cast<const float4*>(W + k * H + c0);
        float4 w1 = *reinterpret_cast<const float4*>(W + k * H + c0 + 4);
        F2 w[4];
        w[0].f = make_float2(w0.x, w0.y);
        w[1].f = make_float2(w0.z, w0.w);
        w[2].f = make_float2(w1.x, w1.y);
        w[3].f = make_float2(w1.z, w1.w);
#pragma unroll
        for (int r = 0; r < 4; ++r) {
            F2 a = f2bcast(in[(r0 + r) * H + k]);
#pragma unroll
            for (int p = 0; p < 4; ++p) acc[r][p] = f2fma(a, w[p], acc[r][p]);
        }
    }
}

__device__ __forceinline__ void acc_zero(F2 (&acc)[4][4]) {
#pragma unroll
    for (int r = 0; r < 4; ++r)
#pragma unroll
        for (int p = 0; p < 4; ++p) { acc[r][p].f.x = 0.f; acc[r][p].f.y = 0.f; }
}

__device__ __forceinline__ void acc_bias(F2 (&acc)[4][4], const float* __restrict__ bias,
                                         int c0, float scale) {
#pragma unroll
    for (int p = 0; p < 4; ++p) {
        float2 b = *reinterpret_cast<const float2*>(bias + c0 + 2 * p);
        F2 v; v.f.x = b.x * scale; v.f.y = b.y * scale;
#pragma unroll
        for (int r = 0; r < 4; ++r) acc[r][p] = v;
    }
}

__device__ __forceinline__ void acc_store(float* __restrict__ out, F2 (&acc)[4][4],
                                          int r0, int c0, bool relu) {
#pragma unroll
    for (int r = 0; r < 4; ++r)
#pragma unroll
        for (int p = 0; p < 4; ++p) {
            float2 v = acc[r][p].f;
            if (relu) { v.x = fmaxf(v.x, 0.f); v.y = fmaxf(v.y, 0.f); }
            *reinterpret_cast<float2*>(out + (r0 + r) * H + c0 + 2 * p) = v;
        }
}

__global__ void __launch_bounds__(THREADS)
rrn_kernel(const int* __restrict__ sources, const int* __restrict__ targets,
           const int* __restrict__ types, const int* __restrict__ diffs,
           const int* __restrict__ question,
           const float* __restrict__ pre_w1, const float* __restrict__ pre_b1,
           const float* __restrict__ pre_w2, const float* __restrict__ pre_b2,
           const float* __restrict__ msg_w1, const float* __restrict__ msg_b1,
           const float* __restrict__ msg_w2, const float* __restrict__ msg_b2,
           const float* __restrict__ node_w1, const float* __restrict__ node_b1,
           const float* __restrict__ node_w2, const float* __restrict__ node_b2,
           const float* __restrict__ out_w1, const float* __restrict__ out_b1,
           const float* __restrict__ out_w2, const float* __restrict__ out_b2,
           float* __restrict__ out)
{
    extern __shared__ float sm[];
    float* sh_h = sm;
    float* sh_x = sm + MROWS * H;
    float* sh_A = sm + 2 * MROWS * H;
    float* sh_B = sm + 3 * MROWS * H;

    const int t   = threadIdx.x;
    const int cta = blockIdx.x;
    const int r0  = (t >> 4) * 4;   // 8 row-groups x 4 rows
    const int c0  = (t & 15) * 8;   // 16 col-groups x 8 cols

    // ---- pre-MLP hidden = relu(one-hot gather of pre_w1 rows + b1) -> sh_A
    {
        const int c  = t;
        const float b1 = pre_b1[c];
        for (int m = 0; m < MROWS; ++m) {
            const int node = cta * MROWS + m;
            const int b    = node >> 3;
            const int s    = sources[node];
            const int tg   = targets[node];
            const int ty   = types[node];
            const int d    = diffs[node];
            const int q    = question[b];
            float v = pre_w1[s * H + c] + pre_w1[(8 + tg) * H + c]
                    + pre_w1[(16 + ty) * H + c] + pre_w1[(19 + d) * H + c]
                    + pre_w1[(119 + q) * H + c] + b1;
            sh_A[m * H + c] = fmaxf(v, 0.f);
        }
    }
    __syncthreads();

    // ---- x = hidden @ pre_w2 + pre_b2 ;  h = x
    {
        F2 acc[4][4];
        acc_bias(acc, pre_b2, c0, 1.0f);
        gemm_acc(sh_A, pre_w2, acc, r0, c0);
        acc_store(sh_x, acc, r0, c0, false);
        acc_store(sh_h, acc, r0, c0, false);
    }
    __syncthreads();

    for (int step = 0; step < NSTEPS; ++step) {
        // A = h @ msg_w1[0:128]   (bias added later in the relu-sum)
        {
            F2 acc[4][4]; acc_zero(acc);
            gemm_acc(sh_h, msg_w1, acc, r0, c0);
            acc_store(sh_A, acc, r0, c0, false);
        }
        // B = h @ msg_w1[128:256]
        {
            F2 acc[4][4]; acc_zero(acc);
            gemm_acc(sh_h, msg_w1 + 128 * H, acc, r0, c0);
            acc_store(sh_B, acc, r0, c0, false);
        }
        __syncthreads();

        // S_i = sum_{j != i} relu(A_i + B_j + b1)   (in place into sh_A)
        {
            const int c  = t;
            const float b1 = msg_b1[c];
            for (int g = 0; g < NG; ++g) {
                float bb[8];
#pragma unroll
                for (int j = 0; j < 8; ++j) bb[j] = sh_B[(g * 8 + j) * H + c];
#pragma unroll
                for (int i = 0; i < 8; ++i) {
                    const float a = sh_A[(g * 8 + i) * H + c];
                    float ssum = 0.f;
#pragma unroll
                    for (int j = 0; j < 8; ++j) ssum += fmaxf(a + bb[j] + b1, 0.f);
                    ssum -= fmaxf(a + bb[i] + b1, 0.f);  // drop self-edge
                    sh_A[(g * 8 + i) * H + c] = ssum;
                }
            }
        }
        __syncthreads();

        // m_agg = S @ msg_w2 + 7*msg_b2  -> sh_B
        {
            F2 acc[4][4];
            acc_bias(acc, msg_b2, c0, 7.0f);
            gemm_acc(sh_A, msg_w2, acc, r0, c0);
            acc_store(sh_B, acc, r0, c0, false);
        }
        __syncthreads();

        // hidden = relu(x@Wn1a + h@Wn1b + magg@Wn1c + node_b1) -> sh_A
        {
            F2 acc[4][4];
            acc_bias(acc, node_b1, c0, 1.0f);
            gemm_acc(sh_x, node_w1,            acc, r0, c0);
            gemm_acc(sh_h, node_w1 + 128 * H,  acc, r0, c0);
            gemm_acc(sh_B, node_w1 + 256 * H,  acc, r0, c0);
            acc_store(sh_A, acc, r0, c0, true);
        }
        __syncthreads();

        // h_new = hidden @ node_w2 + node_b2 -> sh_h
        {
            F2 acc[4][4];
            acc_bias(acc, node_b2, c0, 1.0f);
            gemm_acc(sh_A, node_w2, acc, r0, c0);
            acc_store(sh_h, acc, r0, c0, false);
        }
        __syncthreads();

        // pooled[g] = sum over 8 nodes of h_new  -> sh_B rows 0..3
        {
            const int c = t;
#pragma unroll
            for (int g = 0; g < NG; ++g) {
                float p = 0.f;
#pragma unroll
                for (int v = 0; v < 8; ++v) p += sh_h[(g * 8 + v) * H + c];
                sh_B[g * H + c] = p;
            }
        }
        __syncthreads();

        // out hidden = relu(pooled @ out_w1 + out_b1) -> sh_B rows 4..7
        {
            const int c = t;
            float acc[NG];
            const float ob = out_b1[c];
#pragma unroll
            for (int g = 0; g < NG; ++g) acc[g] = ob;
#pragma unroll 4
            for (int k = 0; k < H; ++k) {
                const float w = out_w1[k * H + c];
#pragma unroll
                for (int g = 0; g < NG; ++g) acc[g] += sh_B[g * H + k] * w;
            }
#pragma unroll
            for (int g = 0; g < NG; ++g) sh_B[(4 + g) * H + c] = fmaxf(acc[g], 0.f);
        }
        __syncthreads();

        // logits = oh @ out_w2 + out_b2 -> gmem  (shape [step][bs][100])
        if (t < 100) {
            const int j = t;
            float acc[NG];
            const float ob = out_b2[j];
#pragma unroll
            for (int g = 0; g < NG; ++g) acc[g] = ob;
#pragma unroll 4
            for (int k = 0; k < H; ++k) {
                const float w = out_w2[k * 100 + j];
#pragma unroll
                for (int g = 0; g < NG; ++g) acc[g] += sh_B[(4 + g) * H + k] * w;
            }
#pragma unroll
            for (int g = 0; g < NG; ++g)
                out[(step * BS + cta * NG + g) * 100 + j] = acc[g];
        }
        __syncthreads();   // protect sh_A/sh_B before next step's GEMM writes
    }
}

extern "C" void kernel_launch(void* const* d_in, const int* in_sizes, int n_in,
                              void* d_out, int out_size) {
    (void)in_sizes; (void)n_in; (void)out_size;
    const int*   sources  = (const int*)  d_in[0];
    const int*   targets  = (const int*)  d_in[1];
    const int*   types    = (const int*)  d_in[2];
    const int*   diffs    = (const int*)  d_in[3];
    const int*   question = (const int*)  d_in[4];
    const float* pre_w1   = (const float*)d_in[5];
    const float* pre_b1   = (const float*)d_in[6];
    const float* pre_w2   = (const float*)d_in[7];
    const float* pre_b2   = (const float*)d_in[8];
    const float* msg_w1   = (const float*)d_in[9];
    const float* msg_b1   = (const float*)d_in[10];
    const float* msg_w2   = (const float*)d_in[11];
    const float* msg_b2   = (const float*)d_in[12];
    const float* node_w1  = (const float*)d_in[13];
    const float* node_b1  = (const float*)d_in[14];
    const float* node_w2  = (const float*)d_in[15];
    const float* node_b2  = (const float*)d_in[16];
    const float* out_w1   = (const float*)d_in[17];
    const float* out_b1   = (const float*)d_in[18];
    const float* out_w2   = (const float*)d_in[19];
    const float* out_b2   = (const float*)d_in[20];

    const size_t smem = 4 * MROWS * H * sizeof(float);  // 64 KB
    cudaFuncSetAttribute(rrn_kernel, cudaFuncAttributeMaxDynamicSharedMemorySize,
                         (int)smem);

    rrn_kernel<<<BS / NG, THREADS, smem>>>(
        sources, targets, types, diffs, question,
        pre_w1, pre_b1, pre_w2, pre_b2,
        msg_w1, msg_b1, msg_w2, msg_b2,
        node_w1, node_b1, node_w2, node_b2,
        out_w1, out_b1, out_w2, out_b2,
        (float*)d_out);
}